// round 1
// baseline (speedup 1.0000x reference)
#include <cuda_runtime.h>
#include <math.h>

#define HIDDEN 2048
#define NH 32
#define NKV 8
#define HD 64
#define BB 2
#define SEQ 2048
#define BSTOK (BB*SEQ)

// Scratch (static device globals; no allocation allowed)
__device__ float g_Q[(size_t)BSTOK * HIDDEN];        // [b,s,32,64]
__device__ float g_K[(size_t)BSTOK * NKV * HD];      // [b,s,8,64]
__device__ float g_V[(size_t)BSTOK * NKV * HD];      // [b,s,8,64]
__device__ float g_O[(size_t)BSTOK * HIDDEN];        // [b,s,32,64]

// ---------------------------------------------------------------------------
// Classic 128x128x8 fp32 SGEMM, 256 threads, 8x8 per thread.
// Row-major A[M,K] @ B[K,N] -> C[M,N]. Requires M%128==0, N%128==0, K%8==0.
// ---------------------------------------------------------------------------
__global__ __launch_bounds__(256) void sgemm128(
    const float* __restrict__ A, const float* __restrict__ B,
    float* __restrict__ C, int M, int N, int K) {
    __shared__ float As[8][128];   // transposed A tile: As[k][m]
    __shared__ float Bs[8][128];   // Bs[k][n]

    const int tid = threadIdx.x;
    const int tr  = tid >> 4;           // 0..15 (row group)
    const int tc  = tid & 15;           // 0..15 (col group)
    const int arow = tid >> 1;          // 0..127
    const int acol = (tid & 1) << 2;    // 0 or 4
    const int brow = tid >> 5;          // 0..7
    const int bcol = (tid & 31) << 2;   // 0..124

    const float* Ab = A + (size_t)blockIdx.y * 128 * K;
    const float* Bb = B + (size_t)blockIdx.x * 128;

    float acc[8][8];
    #pragma unroll
    for (int i = 0; i < 8; i++)
        #pragma unroll
        for (int j = 0; j < 8; j++) acc[i][j] = 0.f;

    for (int k0 = 0; k0 < K; k0 += 8) {
        float4 av = *(const float4*)(Ab + (size_t)arow * K + k0 + acol);
        As[acol + 0][arow] = av.x;
        As[acol + 1][arow] = av.y;
        As[acol + 2][arow] = av.z;
        As[acol + 3][arow] = av.w;
        *(float4*)&Bs[brow][bcol] =
            *(const float4*)(Bb + (size_t)(k0 + brow) * N + bcol);
        __syncthreads();

        #pragma unroll
        for (int kk = 0; kk < 8; kk++) {
            float4 a0 = *(const float4*)&As[kk][tr * 8];
            float4 a1 = *(const float4*)&As[kk][tr * 8 + 4];
            float4 b0 = *(const float4*)&Bs[kk][tc * 8];
            float4 b1 = *(const float4*)&Bs[kk][tc * 8 + 4];
            float ar[8] = {a0.x, a0.y, a0.z, a0.w, a1.x, a1.y, a1.z, a1.w};
            float br[8] = {b0.x, b0.y, b0.z, b0.w, b1.x, b1.y, b1.z, b1.w};
            #pragma unroll
            for (int i = 0; i < 8; i++)
                #pragma unroll
                for (int j = 0; j < 8; j++)
                    acc[i][j] += ar[i] * br[j];
        }
        __syncthreads();
    }

    float* Cb = C + (size_t)(blockIdx.y * 128 + tr * 8) * N + blockIdx.x * 128 + tc * 8;
    #pragma unroll
    for (int i = 0; i < 8; i++) {
        float4 c0 = {acc[i][0], acc[i][1], acc[i][2], acc[i][3]};
        float4 c1 = {acc[i][4], acc[i][5], acc[i][6], acc[i][7]};
        *(float4*)(Cb + (size_t)i * N)     = c0;
        *(float4*)(Cb + (size_t)i * N + 4) = c1;
    }
}

// ---------------------------------------------------------------------------
// RoPE in-place. X layout [b, s, nheads, 64]. Double-precision sincos so the
// result is immune to fast-math range reduction (pos up to 4095).
// One thread per (token, head, pair i<32).
// ---------------------------------------------------------------------------
__global__ void rope_kernel(float* __restrict__ X,
                            const int* __restrict__ pos_ids, int nheads) {
    int idx = blockIdx.x * blockDim.x + threadIdx.x;
    int total = BSTOK * nheads * 32;
    if (idx >= total) return;
    int i  = idx & 31;
    int h  = (idx >> 5) % nheads;
    int bs = idx / (nheads * 32);

    // inv_freq = 10000^(-2i/64) = exp(-i * ln(10000)/32)
    double inv_freq = exp(-(double)i * (9.210340371976184 / 32.0));
    double ang = (double)pos_ids[bs] * inv_freq;
    double sd, cd;
    sincos(ang, &sd, &cd);
    float c = (float)cd, sn = (float)sd;

    float* p = X + ((size_t)bs * nheads + h) * HD;
    float x1 = p[i];
    float x2 = p[i + 32];
    p[i]      = x1 * c - x2 * sn;
    p[i + 32] = x2 * c + x1 * sn;
}

// ---------------------------------------------------------------------------
// Causal flash attention, thread-per-query. BQ=64 queries per block (one per
// thread), BK=64 keys per tile, d=64 in registers. GQA: head h -> kv head h/4.
// Q/O layout [b,s,32,64]; K/V layout [b,s,8,64].
// ---------------------------------------------------------------------------
__global__ __launch_bounds__(64) void flash_attn(
    const float* __restrict__ Q, const float* __restrict__ Kg,
    const float* __restrict__ Vg, float* __restrict__ O) {
    __shared__ float Ks[64][64];
    __shared__ float Vs[64][64];
    __shared__ float Sc[64][64];   // [key][thread] -> conflict-free both ways

    const int t  = threadIdx.x;
    const int qb = blockIdx.x;
    const int h  = blockIdx.y;
    const int b  = blockIdx.z;
    const int hkv = h >> 2;
    const int qi  = qb * 64 + t;

    const float* qptr = Q + (((size_t)(b * SEQ + qi)) * NH + h) * HD;
    float q[64];
    #pragma unroll
    for (int d4 = 0; d4 < 16; d4++) {
        float4 v = ((const float4*)qptr)[d4];
        q[4 * d4 + 0] = v.x; q[4 * d4 + 1] = v.y;
        q[4 * d4 + 2] = v.z; q[4 * d4 + 3] = v.w;
    }

    float acc[64];
    #pragma unroll
    for (int d = 0; d < 64; d++) acc[d] = 0.f;
    float m = -1e30f, l = 0.f;
    const float scale = 0.125f;   // 1/sqrt(64)

    for (int kt = 0; kt <= qb; kt++) {
        const int k0 = kt * 64;
        // Cooperative tile load: 1024 float4 per tile, 16 per thread.
        #pragma unroll
        for (int it = 0; it < 16; it++) {
            int idx = it * 64 + t;
            int row = idx >> 4;
            int c4  = idx & 15;
            size_t base = (((size_t)(b * SEQ + k0 + row)) * NKV + hkv) * HD;
            ((float4*)&Ks[row][0])[c4] = ((const float4*)(Kg + base))[c4];
            ((float4*)&Vs[row][0])[c4] = ((const float4*)(Vg + base))[c4];
        }
        __syncthreads();

        const bool diag = (kt == qb);
        float tmax = -1e30f;
        for (int j = 0; j < 64; j++) {
            float s = 0.f;
            const float4* kr = (const float4*)&Ks[j][0];
            #pragma unroll
            for (int d4 = 0; d4 < 16; d4++) {
                float4 kv = kr[d4];
                s += q[4 * d4 + 0] * kv.x + q[4 * d4 + 1] * kv.y
                   + q[4 * d4 + 2] * kv.z + q[4 * d4 + 3] * kv.w;
            }
            s *= scale;
            if (diag && (k0 + j > qi)) s = -1e30f;
            Sc[j][t] = s;
            tmax = fmaxf(tmax, s);
        }

        float m_new = fmaxf(m, tmax);
        float corr  = __expf(m - m_new);
        l *= corr;
        #pragma unroll
        for (int d = 0; d < 64; d++) acc[d] *= corr;

        for (int j = 0; j < 64; j++) {
            float p = __expf(Sc[j][t] - m_new);
            l += p;
            const float4* vr = (const float4*)&Vs[j][0];
            #pragma unroll
            for (int d4 = 0; d4 < 16; d4++) {
                float4 vv = vr[d4];
                acc[4 * d4 + 0] += p * vv.x;
                acc[4 * d4 + 1] += p * vv.y;
                acc[4 * d4 + 2] += p * vv.z;
                acc[4 * d4 + 3] += p * vv.w;
            }
        }
        m = m_new;
        __syncthreads();
    }

    float inv_l = 1.f / l;
    float* optr = O + (((size_t)(b * SEQ + qi)) * NH + h) * HD;
    #pragma unroll
    for (int d4 = 0; d4 < 16; d4++) {
        float4 v;
        v.x = acc[4 * d4 + 0] * inv_l;
        v.y = acc[4 * d4 + 1] * inv_l;
        v.z = acc[4 * d4 + 2] * inv_l;
        v.w = acc[4 * d4 + 3] * inv_l;
        ((float4*)optr)[d4] = v;
    }
}

// ---------------------------------------------------------------------------
// Launch sequence (all on the capture stream, no sync, no alloc)
// ---------------------------------------------------------------------------
extern "C" void kernel_launch(void* const* d_in, const int* in_sizes, int n_in,
                              void* d_out, int out_size) {
    const float* x   = (const float*)d_in[0];   // [2,2048,2048]
    const float* Wq  = (const float*)d_in[1];   // [2048,2048]
    const float* Wk  = (const float*)d_in[2];   // [2048,512]
    const float* Wv  = (const float*)d_in[3];   // [2048,512]
    const float* Wo  = (const float*)d_in[4];   // [2048,2048]
    const int*   pos = (const int*)d_in[5];     // [2,2048]
    float* out = (float*)d_out;

    float *Qp, *Kp, *Vp, *Op;
    cudaGetSymbolAddress((void**)&Qp, g_Q);
    cudaGetSymbolAddress((void**)&Kp, g_K);
    cudaGetSymbolAddress((void**)&Vp, g_V);
    cudaGetSymbolAddress((void**)&Op, g_O);

    const int M = BSTOK;           // 4096
    dim3 blk(256);

    // QKV projections
    sgemm128<<<dim3(HIDDEN / 128, M / 128), blk>>>(x, Wq, Qp, M, HIDDEN, HIDDEN);
    sgemm128<<<dim3((NKV * HD) / 128, M / 128), blk>>>(x, Wk, Kp, M, NKV * HD, HIDDEN);
    sgemm128<<<dim3((NKV * HD) / 128, M / 128), blk>>>(x, Wv, Vp, M, NKV * HD, HIDDEN);

    // RoPE (Q: 32 heads, K: 8 heads)
    {
        int totalQ = BSTOK * NH * 32;
        int totalK = BSTOK * NKV * 32;
        rope_kernel<<<(totalQ + 255) / 256, 256>>>(Qp, pos, NH);
        rope_kernel<<<(totalK + 255) / 256, 256>>>(Kp, pos, NKV);
    }

    // Causal flash attention
    flash_attn<<<dim3(SEQ / 64, NH, BB), 64>>>(Qp, Kp, Vp, Op);

    // Output projection
    sgemm128<<<dim3(HIDDEN / 128, M / 128), blk>>>(Op, Wo, out, M, HIDDEN, HIDDEN);
}

// round 3
// speedup vs baseline: 1.8888x; 1.8888x over previous
#include <cuda_runtime.h>
#include <math.h>
#include <stdint.h>

#define HIDDEN 2048
#define NH 32
#define NKV 8
#define HD 64
#define BB 2
#define SEQ 2048
#define BSTOK (BB*SEQ)

// ---------------------------------------------------------------------------
// Scratch (static device globals; no allocation allowed)
// ---------------------------------------------------------------------------
__device__ float g_Q[(size_t)BSTOK * HIDDEN];        // [b,s,32,64]
__device__ float g_K[(size_t)BSTOK * NKV * HD];      // [b,s,8,64]
__device__ float g_V[(size_t)BSTOK * NKV * HD];      // [b,s,8,64]
__device__ float g_O[(size_t)BSTOK * HIDDEN];        // [b,s,32,64]
__device__ float g_WtQ[(size_t)HIDDEN * HIDDEN];     // Wq^T [N,K]
__device__ float g_WtK[(size_t)(NKV*HD) * HIDDEN];
__device__ float g_WtV[(size_t)(NKV*HD) * HIDDEN];
__device__ float g_WtO[(size_t)HIDDEN * HIDDEN];
__device__ float g_cos[BSTOK * 32];
__device__ float g_sin[BSTOK * 32];

__device__ __forceinline__ uint32_t f2tf32(float x) {
    uint32_t r;
    asm("cvt.rna.tf32.f32 %0, %1;" : "=r"(r) : "f"(x));
    return r;
}

// ---------------------------------------------------------------------------
// tf32 mma.sync GEMM: C[M,N] = A[M,K] @ Bt[N,K]^T.
// CTA 128x128, 256 threads (8 warps, 2Mx4N), warp tile 64x32.
// Smem tiles [row][k] stride 36 (conflict-free fragment loads).
// Double-buffered K-chunks of 32 with register-staged prefetch.
// Requires M%128==0, N%128==0, K%32==0.
// ---------------------------------------------------------------------------
#define TSTR 36
#define TILEF (128 * TSTR)                 // floats per tile
#define GEMM_SMEM_BYTES (4 * TILEF * 4)    // A0,B0,A1,B1 = 73728 B

__global__ __launch_bounds__(256, 1) void gemm_mma(
    const float* __restrict__ A, const float* __restrict__ Bt,
    float* __restrict__ C, int M, int N, int K) {
    extern __shared__ float sm[];
    const int tid  = threadIdx.x;
    const int wid  = tid >> 5;
    const int lane = tid & 31;
    const int gid  = lane >> 2;       // 0..7
    const int tid4 = lane & 3;        // 0..3
    const int wm   = wid & 1;         // 0..1  (64 rows each)
    const int wn   = wid >> 1;        // 0..3  (32 cols each)
    const int m0 = blockIdx.y * 128;
    const int n0 = blockIdx.x * 128;

    // cooperative-load indexing: 1024 float4 per tile, 4 per thread
    int lrow[4], lc4[4];
    #pragma unroll
    for (int i = 0; i < 4; i++) {
        int lin = i * 256 + tid;
        lrow[i] = lin >> 3;
        lc4[i]  = lin & 7;
    }

    const float* Ag = A  + (size_t)m0 * K;
    const float* Bg = Bt + (size_t)n0 * K;

    float acc[4][4][4];
    #pragma unroll
    for (int mt = 0; mt < 4; mt++)
        #pragma unroll
        for (int nt = 0; nt < 4; nt++)
            #pragma unroll
            for (int c = 0; c < 4; c++) acc[mt][nt][c] = 0.f;

    // load chunk 0
    #pragma unroll
    for (int i = 0; i < 4; i++) {
        float4 va = *(const float4*)(Ag + (size_t)lrow[i] * K + lc4[i] * 4);
        float4 vb = *(const float4*)(Bg + (size_t)lrow[i] * K + lc4[i] * 4);
        uint4 ua = { f2tf32(va.x), f2tf32(va.y), f2tf32(va.z), f2tf32(va.w) };
        uint4 ub = { f2tf32(vb.x), f2tf32(vb.y), f2tf32(vb.z), f2tf32(vb.w) };
        *(uint4*)(sm + lrow[i] * TSTR + lc4[i] * 4)         = ua;
        *(uint4*)(sm + TILEF + lrow[i] * TSTR + lc4[i] * 4) = ub;
    }
    __syncthreads();

    const int nch = K / 32;
    for (int ch = 0; ch < nch; ch++) {
        const int cur = ch & 1;
        const float* Ac = sm + cur * 2 * TILEF;
        const float* Bc = Ac + TILEF;

        // prefetch next chunk to regs
        float4 pa[4], pb[4];
        if (ch + 1 < nch) {
            const int kb = (ch + 1) * 32;
            #pragma unroll
            for (int i = 0; i < 4; i++) {
                pa[i] = *(const float4*)(Ag + (size_t)lrow[i] * K + kb + lc4[i] * 4);
                pb[i] = *(const float4*)(Bg + (size_t)lrow[i] * K + kb + lc4[i] * 4);
            }
        }

        // 4 k8-steps of mma
        #pragma unroll
        for (int ks = 0; ks < 4; ks++) {
            const int k0 = ks * 8;
            uint32_t af[4][4], bf[4][2];
            #pragma unroll
            for (int mt = 0; mt < 4; mt++) {
                const float* ap = Ac + (wm * 64 + mt * 16 + gid) * TSTR + k0 + tid4;
                af[mt][0] = __float_as_uint(ap[0]);
                af[mt][1] = __float_as_uint(ap[8 * TSTR]);
                af[mt][2] = __float_as_uint(ap[4]);
                af[mt][3] = __float_as_uint(ap[8 * TSTR + 4]);
            }
            #pragma unroll
            for (int nt = 0; nt < 4; nt++) {
                const float* bp = Bc + (wn * 32 + nt * 8 + gid) * TSTR + k0 + tid4;
                bf[nt][0] = __float_as_uint(bp[0]);
                bf[nt][1] = __float_as_uint(bp[4]);
            }
            #pragma unroll
            for (int mt = 0; mt < 4; mt++)
                #pragma unroll
                for (int nt = 0; nt < 4; nt++) {
                    float* c = acc[mt][nt];
                    asm volatile(
                        "mma.sync.aligned.m16n8k8.row.col.f32.tf32.tf32.f32 "
                        "{%0,%1,%2,%3}, {%4,%5,%6,%7}, {%8,%9}, {%0,%1,%2,%3};"
                        : "+f"(c[0]), "+f"(c[1]), "+f"(c[2]), "+f"(c[3])
                        : "r"(af[mt][0]), "r"(af[mt][1]), "r"(af[mt][2]), "r"(af[mt][3]),
                          "r"(bf[nt][0]), "r"(bf[nt][1]));
                }
        }

        // store prefetched chunk into the other buffer
        if (ch + 1 < nch) {
            float* An = sm + (1 - cur) * 2 * TILEF;
            float* Bn = An + TILEF;
            #pragma unroll
            for (int i = 0; i < 4; i++) {
                uint4 ua = { f2tf32(pa[i].x), f2tf32(pa[i].y), f2tf32(pa[i].z), f2tf32(pa[i].w) };
                uint4 ub = { f2tf32(pb[i].x), f2tf32(pb[i].y), f2tf32(pb[i].z), f2tf32(pb[i].w) };
                *(uint4*)(An + lrow[i] * TSTR + lc4[i] * 4) = ua;
                *(uint4*)(Bn + lrow[i] * TSTR + lc4[i] * 4) = ub;
            }
        }
        __syncthreads();
    }

    // epilogue: direct float2 stores
    #pragma unroll
    for (int mt = 0; mt < 4; mt++) {
        const int r = m0 + wm * 64 + mt * 16 + gid;
        #pragma unroll
        for (int nt = 0; nt < 4; nt++) {
            const int col = n0 + wn * 32 + nt * 8 + tid4 * 2;
            float2 v0 = { acc[mt][nt][0], acc[mt][nt][1] };
            float2 v1 = { acc[mt][nt][2], acc[mt][nt][3] };
            *(float2*)(C + (size_t)r * N + col)       = v0;
            *(float2*)(C + (size_t)(r + 8) * N + col) = v1;
        }
    }
}

// ---------------------------------------------------------------------------
// Weight transpose: Wt[n][k] = W[k][n].  W is R x C row-major.
// ---------------------------------------------------------------------------
__global__ void transpose_k(const float* __restrict__ W, float* __restrict__ Wt,
                            int R, int C) {
    __shared__ float tile[32][33];
    int c0 = blockIdx.x * 32, r0 = blockIdx.y * 32;
    int tx = threadIdx.x;
    for (int j = threadIdx.y; j < 32; j += 8)
        tile[j][tx] = W[(size_t)(r0 + j) * C + c0 + tx];
    __syncthreads();
    for (int j = threadIdx.y; j < 32; j += 8)
        Wt[(size_t)(c0 + j) * R + r0 + tx] = tile[tx][j];
}

// ---------------------------------------------------------------------------
// RoPE: fp64 table once per (token, freq), fp32 apply.
// ---------------------------------------------------------------------------
__global__ void rope_table(const int* __restrict__ pos) {
    int idx = blockIdx.x * blockDim.x + threadIdx.x;
    if (idx >= BSTOK * 32) return;
    int i = idx & 31, bs = idx >> 5;
    double inv_freq = exp(-(double)i * (9.210340371976184 / 32.0));
    double a = (double)pos[bs] * inv_freq;
    double s, c;
    sincos(a, &s, &c);
    g_cos[idx] = (float)c;
    g_sin[idx] = (float)s;
}

__global__ void rope_apply(float* __restrict__ X, int nheads) {
    int idx = blockIdx.x * blockDim.x + threadIdx.x;
    int total = BSTOK * nheads * 32;
    if (idx >= total) return;
    int i  = idx & 31;
    int h  = (idx >> 5) % nheads;
    int bs = idx / (nheads * 32);
    float c  = g_cos[bs * 32 + i];
    float sn = g_sin[bs * 32 + i];
    float* p = X + ((size_t)bs * nheads + h) * HD;
    float x1 = p[i], x2 = p[i + 32];
    p[i]      = x1 * c - x2 * sn;
    p[i + 32] = x2 * c + x1 * sn;
}

// ---------------------------------------------------------------------------
// Causal flash attention, thread-per-query (unchanged; R1-validated).
// ---------------------------------------------------------------------------
__global__ __launch_bounds__(64) void flash_attn(
    const float* __restrict__ Q, const float* __restrict__ Kg,
    const float* __restrict__ Vg, float* __restrict__ O) {
    __shared__ float Ks[64][64];
    __shared__ float Vs[64][64];
    __shared__ float Sc[64][64];

    const int t  = threadIdx.x;
    const int qb = blockIdx.x;
    const int h  = blockIdx.y;
    const int b  = blockIdx.z;
    const int hkv = h >> 2;
    const int qi  = qb * 64 + t;

    const float* qptr = Q + (((size_t)(b * SEQ + qi)) * NH + h) * HD;
    float q[64];
    #pragma unroll
    for (int d4 = 0; d4 < 16; d4++) {
        float4 v = ((const float4*)qptr)[d4];
        q[4 * d4 + 0] = v.x; q[4 * d4 + 1] = v.y;
        q[4 * d4 + 2] = v.z; q[4 * d4 + 3] = v.w;
    }

    float acc[64];
    #pragma unroll
    for (int d = 0; d < 64; d++) acc[d] = 0.f;
    float m = -1e30f, l = 0.f;
    const float scale = 0.125f;

    for (int kt = 0; kt <= qb; kt++) {
        const int k0 = kt * 64;
        #pragma unroll
        for (int it = 0; it < 16; it++) {
            int idx = it * 64 + t;
            int row = idx >> 4;
            int c4  = idx & 15;
            size_t base = (((size_t)(b * SEQ + k0 + row)) * NKV + hkv) * HD;
            ((float4*)&Ks[row][0])[c4] = ((const float4*)(Kg + base))[c4];
            ((float4*)&Vs[row][0])[c4] = ((const float4*)(Vg + base))[c4];
        }
        __syncthreads();

        const bool diag = (kt == qb);
        float tmax = -1e30f;
        for (int j = 0; j < 64; j++) {
            float s = 0.f;
            const float4* kr = (const float4*)&Ks[j][0];
            #pragma unroll
            for (int d4 = 0; d4 < 16; d4++) {
                float4 kv = kr[d4];
                s += q[4 * d4 + 0] * kv.x + q[4 * d4 + 1] * kv.y
                   + q[4 * d4 + 2] * kv.z + q[4 * d4 + 3] * kv.w;
            }
            s *= scale;
            if (diag && (k0 + j > qi)) s = -1e30f;
            Sc[j][t] = s;
            tmax = fmaxf(tmax, s);
        }

        float m_new = fmaxf(m, tmax);
        float corr  = __expf(m - m_new);
        l *= corr;
        #pragma unroll
        for (int d = 0; d < 64; d++) acc[d] *= corr;

        for (int j = 0; j < 64; j++) {
            float p = __expf(Sc[j][t] - m_new);
            l += p;
            const float4* vr = (const float4*)&Vs[j][0];
            #pragma unroll
            for (int d4 = 0; d4 < 16; d4++) {
                float4 vv = vr[d4];
                acc[4 * d4 + 0] += p * vv.x;
                acc[4 * d4 + 1] += p * vv.y;
                acc[4 * d4 + 2] += p * vv.z;
                acc[4 * d4 + 3] += p * vv.w;
            }
        }
        m = m_new;
        __syncthreads();
    }

    float inv_l = 1.f / l;
    float* optr = O + (((size_t)(b * SEQ + qi)) * NH + h) * HD;
    #pragma unroll
    for (int d4 = 0; d4 < 16; d4++) {
        float4 v;
        v.x = acc[4 * d4 + 0] * inv_l;
        v.y = acc[4 * d4 + 1] * inv_l;
        v.z = acc[4 * d4 + 2] * inv_l;
        v.w = acc[4 * d4 + 3] * inv_l;
        ((float4*)optr)[d4] = v;
    }
}

// ---------------------------------------------------------------------------
// Launch sequence
// ---------------------------------------------------------------------------
extern "C" void kernel_launch(void* const* d_in, const int* in_sizes, int n_in,
                              void* d_out, int out_size) {
    const float* x   = (const float*)d_in[0];
    const float* Wq  = (const float*)d_in[1];
    const float* Wk  = (const float*)d_in[2];
    const float* Wv  = (const float*)d_in[3];
    const float* Wo  = (const float*)d_in[4];
    const int*   pos = (const int*)d_in[5];
    float* out = (float*)d_out;

    float *Qp, *Kp, *Vp, *Op, *WtQ, *WtK, *WtV, *WtO;
    cudaGetSymbolAddress((void**)&Qp,  g_Q);
    cudaGetSymbolAddress((void**)&Kp,  g_K);
    cudaGetSymbolAddress((void**)&Vp,  g_V);
    cudaGetSymbolAddress((void**)&Op,  g_O);
    cudaGetSymbolAddress((void**)&WtQ, g_WtQ);
    cudaGetSymbolAddress((void**)&WtK, g_WtK);
    cudaGetSymbolAddress((void**)&WtV, g_WtV);
    cudaGetSymbolAddress((void**)&WtO, g_WtO);

    cudaFuncSetAttribute(gemm_mma, cudaFuncAttributeMaxDynamicSharedMemorySize,
                         GEMM_SMEM_BYTES);

    const int M = BSTOK;        // 4096
    dim3 tb(32, 8);

    // Weight transposes (W[K,N] -> Wt[N,K])
    transpose_k<<<dim3(HIDDEN / 32, HIDDEN / 32), tb>>>(Wq, WtQ, HIDDEN, HIDDEN);
    transpose_k<<<dim3((NKV * HD) / 32, HIDDEN / 32), tb>>>(Wk, WtK, HIDDEN, NKV * HD);
    transpose_k<<<dim3((NKV * HD) / 32, HIDDEN / 32), tb>>>(Wv, WtV, HIDDEN, NKV * HD);
    transpose_k<<<dim3(HIDDEN / 32, HIDDEN / 32), tb>>>(Wo, WtO, HIDDEN, HIDDEN);

    // RoPE table
    rope_table<<<(BSTOK * 32 + 255) / 256, 256>>>(pos);

    // QKV projections (tensor-core tf32 mma.sync)
    gemm_mma<<<dim3(HIDDEN / 128, M / 128), 256, GEMM_SMEM_BYTES>>>(
        x, WtQ, Qp, M, HIDDEN, HIDDEN);
    gemm_mma<<<dim3((NKV * HD) / 128, M / 128), 256, GEMM_SMEM_BYTES>>>(
        x, WtK, Kp, M, NKV * HD, HIDDEN);
    gemm_mma<<<dim3((NKV * HD) / 128, M / 128), 256, GEMM_SMEM_BYTES>>>(
        x, WtV, Vp, M, NKV * HD, HIDDEN);

    // RoPE apply
    rope_apply<<<(BSTOK * NH * 32 + 255) / 256, 256>>>(Qp, NH);
    rope_apply<<<(BSTOK * NKV * 32 + 255) / 256, 256>>>(Kp, NKV);

    // Causal flash attention
    flash_attn<<<dim3(SEQ / 64, NH, BB), 64>>>(Qp, Kp, Vp, Op);

    // Output projection
    gemm_mma<<<dim3(HIDDEN / 128, M / 128), 256, GEMM_SMEM_BYTES>>>(
        Op, WtO, out, M, HIDDEN, HIDDEN);
}

// round 4
// speedup vs baseline: 4.0130x; 2.1246x over previous
#include <cuda_runtime.h>
#include <math.h>
#include <stdint.h>

#define HIDDEN 2048
#define NH 32
#define NKV 8
#define HD 64
#define BB 2
#define SEQ 2048
#define BSTOK (BB*SEQ)

// ---------------------------------------------------------------------------
// Scratch (static device globals; no allocation allowed)
// ---------------------------------------------------------------------------
__device__ float g_Q[(size_t)BSTOK * HIDDEN];        // [b,s,32,64]
__device__ float g_K[(size_t)BSTOK * NKV * HD];      // [b,s,8,64]
__device__ float g_V[(size_t)BSTOK * NKV * HD];      // [b,s,8,64]
__device__ float g_O[(size_t)BSTOK * HIDDEN];        // [b,s,32,64]
__device__ float g_WtQ[(size_t)HIDDEN * HIDDEN];     // Wq^T [N,K]
__device__ float g_WtK[(size_t)(NKV*HD) * HIDDEN];
__device__ float g_WtV[(size_t)(NKV*HD) * HIDDEN];
__device__ float g_WtO[(size_t)HIDDEN * HIDDEN];
__device__ float g_cos[BSTOK * 32];
__device__ float g_sin[BSTOK * 32];

__device__ __forceinline__ uint32_t f2tf32(float x) {
    uint32_t r;
    asm("cvt.rna.tf32.f32 %0, %1;" : "=r"(r) : "f"(x));
    return r;
}
__device__ __forceinline__ void mma8(float* c, const uint32_t* a,
                                     uint32_t b0, uint32_t b1) {
    asm volatile(
        "mma.sync.aligned.m16n8k8.row.col.f32.tf32.tf32.f32 "
        "{%0,%1,%2,%3}, {%4,%5,%6,%7}, {%8,%9}, {%0,%1,%2,%3};"
        : "+f"(c[0]), "+f"(c[1]), "+f"(c[2]), "+f"(c[3])
        : "r"(a[0]), "r"(a[1]), "r"(a[2]), "r"(a[3]), "r"(b0), "r"(b1));
}

// ---------------------------------------------------------------------------
// tf32 mma.sync GEMM: C[M,N] = A[M,K] @ Bt[N,K]^T.  (unchanged from R3)
// ---------------------------------------------------------------------------
#define TSTR 36
#define TILEF (128 * TSTR)
#define GEMM_SMEM_BYTES (4 * TILEF * 4)

__global__ __launch_bounds__(256, 1) void gemm_mma(
    const float* __restrict__ A, const float* __restrict__ Bt,
    float* __restrict__ C, int M, int N, int K) {
    extern __shared__ float sm[];
    const int tid  = threadIdx.x;
    const int wid  = tid >> 5;
    const int lane = tid & 31;
    const int gid  = lane >> 2;
    const int tid4 = lane & 3;
    const int wm   = wid & 1;
    const int wn   = wid >> 1;
    const int m0 = blockIdx.y * 128;
    const int n0 = blockIdx.x * 128;

    int lrow[4], lc4[4];
    #pragma unroll
    for (int i = 0; i < 4; i++) {
        int lin = i * 256 + tid;
        lrow[i] = lin >> 3;
        lc4[i]  = lin & 7;
    }

    const float* Ag = A  + (size_t)m0 * K;
    const float* Bg = Bt + (size_t)n0 * K;

    float acc[4][4][4];
    #pragma unroll
    for (int mt = 0; mt < 4; mt++)
        #pragma unroll
        for (int nt = 0; nt < 4; nt++)
            #pragma unroll
            for (int c = 0; c < 4; c++) acc[mt][nt][c] = 0.f;

    #pragma unroll
    for (int i = 0; i < 4; i++) {
        float4 va = *(const float4*)(Ag + (size_t)lrow[i] * K + lc4[i] * 4);
        float4 vb = *(const float4*)(Bg + (size_t)lrow[i] * K + lc4[i] * 4);
        uint4 ua = { f2tf32(va.x), f2tf32(va.y), f2tf32(va.z), f2tf32(va.w) };
        uint4 ub = { f2tf32(vb.x), f2tf32(vb.y), f2tf32(vb.z), f2tf32(vb.w) };
        *(uint4*)(sm + lrow[i] * TSTR + lc4[i] * 4)         = ua;
        *(uint4*)(sm + TILEF + lrow[i] * TSTR + lc4[i] * 4) = ub;
    }
    __syncthreads();

    const int nch = K / 32;
    for (int ch = 0; ch < nch; ch++) {
        const int cur = ch & 1;
        const float* Ac = sm + cur * 2 * TILEF;
        const float* Bc = Ac + TILEF;

        float4 pa[4], pb[4];
        if (ch + 1 < nch) {
            const int kb = (ch + 1) * 32;
            #pragma unroll
            for (int i = 0; i < 4; i++) {
                pa[i] = *(const float4*)(Ag + (size_t)lrow[i] * K + kb + lc4[i] * 4);
                pb[i] = *(const float4*)(Bg + (size_t)lrow[i] * K + kb + lc4[i] * 4);
            }
        }

        #pragma unroll
        for (int ks = 0; ks < 4; ks++) {
            const int k0 = ks * 8;
            uint32_t af[4][4], bf[4][2];
            #pragma unroll
            for (int mt = 0; mt < 4; mt++) {
                const float* ap = Ac + (wm * 64 + mt * 16 + gid) * TSTR + k0 + tid4;
                af[mt][0] = __float_as_uint(ap[0]);
                af[mt][1] = __float_as_uint(ap[8 * TSTR]);
                af[mt][2] = __float_as_uint(ap[4]);
                af[mt][3] = __float_as_uint(ap[8 * TSTR + 4]);
            }
            #pragma unroll
            for (int nt = 0; nt < 4; nt++) {
                const float* bp = Bc + (wn * 32 + nt * 8 + gid) * TSTR + k0 + tid4;
                bf[nt][0] = __float_as_uint(bp[0]);
                bf[nt][1] = __float_as_uint(bp[4]);
            }
            #pragma unroll
            for (int mt = 0; mt < 4; mt++)
                #pragma unroll
                for (int nt = 0; nt < 4; nt++)
                    mma8(acc[mt][nt], af[mt], bf[nt][0], bf[nt][1]);
        }

        if (ch + 1 < nch) {
            float* An = sm + (1 - cur) * 2 * TILEF;
            float* Bn = An + TILEF;
            #pragma unroll
            for (int i = 0; i < 4; i++) {
                uint4 ua = { f2tf32(pa[i].x), f2tf32(pa[i].y), f2tf32(pa[i].z), f2tf32(pa[i].w) };
                uint4 ub = { f2tf32(pb[i].x), f2tf32(pb[i].y), f2tf32(pb[i].z), f2tf32(pb[i].w) };
                *(uint4*)(An + lrow[i] * TSTR + lc4[i] * 4) = ua;
                *(uint4*)(Bn + lrow[i] * TSTR + lc4[i] * 4) = ub;
            }
        }
        __syncthreads();
    }

    #pragma unroll
    for (int mt = 0; mt < 4; mt++) {
        const int r = m0 + wm * 64 + mt * 16 + gid;
        #pragma unroll
        for (int nt = 0; nt < 4; nt++) {
            const int col = n0 + wn * 32 + nt * 8 + tid4 * 2;
            float2 v0 = { acc[mt][nt][0], acc[mt][nt][1] };
            float2 v1 = { acc[mt][nt][2], acc[mt][nt][3] };
            *(float2*)(C + (size_t)r * N + col)       = v0;
            *(float2*)(C + (size_t)(r + 8) * N + col) = v1;
        }
    }
}

// ---------------------------------------------------------------------------
// Weight transpose
// ---------------------------------------------------------------------------
__global__ void transpose_k(const float* __restrict__ W, float* __restrict__ Wt,
                            int R, int C) {
    __shared__ float tile[32][33];
    int c0 = blockIdx.x * 32, r0 = blockIdx.y * 32;
    int tx = threadIdx.x;
    for (int j = threadIdx.y; j < 32; j += 8)
        tile[j][tx] = W[(size_t)(r0 + j) * C + c0 + tx];
    __syncthreads();
    for (int j = threadIdx.y; j < 32; j += 8)
        Wt[(size_t)(c0 + j) * R + r0 + tx] = tile[tx][j];
}

// ---------------------------------------------------------------------------
// RoPE
// ---------------------------------------------------------------------------
__global__ void rope_table(const int* __restrict__ pos) {
    int idx = blockIdx.x * blockDim.x + threadIdx.x;
    if (idx >= BSTOK * 32) return;
    int i = idx & 31, bs = idx >> 5;
    double inv_freq = exp(-(double)i * (9.210340371976184 / 32.0));
    double a = (double)pos[bs] * inv_freq;
    double s, c;
    sincos(a, &s, &c);
    g_cos[idx] = (float)c;
    g_sin[idx] = (float)s;
}

__global__ void rope_apply(float* __restrict__ X, int nheads) {
    int idx = blockIdx.x * blockDim.x + threadIdx.x;
    int total = BSTOK * nheads * 32;
    if (idx >= total) return;
    int i  = idx & 31;
    int h  = (idx >> 5) % nheads;
    int bs = idx / (nheads * 32);
    float c  = g_cos[bs * 32 + i];
    float sn = g_sin[bs * 32 + i];
    float* p = X + ((size_t)bs * nheads + h) * HD;
    float x1 = p[i], x2 = p[i + 32];
    p[i]      = x1 * c - x2 * sn;
    p[i + 32] = x2 * c + x1 * sn;
}

// ---------------------------------------------------------------------------
// Tensor-core causal flash attention.
// CTA: 64 queries (4 warps x 16-row stripes) x 64-key tiles, d=64.
// S = Q K^T and O += P V via tf32 mma.m16n8k8; register softmax;
// P staged through warp-private smem stripe (layout fix-up).
// Strides: K,S = 68 (==4 mod 32), V = 72 (==8 mod 32) -> conflict-free frags.
// ---------------------------------------------------------------------------
#define FST 68
#define FSTV 72
#define FLASH_SMEM ((64*FST + 64*FSTV + 64*FST) * 4)   // 53248 B

__global__ __launch_bounds__(128, 1) void flash_mma(
    const float* __restrict__ Q, const float* __restrict__ Kg,
    const float* __restrict__ Vg, float* __restrict__ O) {
    extern __shared__ float fs[];
    float* Ks = fs;                    // [64][68]
    float* Vs = fs + 64 * FST;         // [64][72]
    float* Ss = Vs + 64 * FSTV;        // [64][68], warp-private 16-row stripes

    const int tid  = threadIdx.x;
    const int warp = tid >> 5;
    const int lane = tid & 31;
    const int gid  = lane >> 2;
    const int tid4 = lane & 3;
    const int qb = blockIdx.x, h = blockIdx.y, b = blockIdx.z;
    const int hkv = h >> 2;
    const int row0 = warp * 16;

    // Stage Q stripe (tf32) into this warp's S region, then cache fragments.
    #pragma unroll
    for (int j = 0; j < 8; j++) {
        int idx = j * 32 + lane;
        int r = idx >> 4, c4 = idx & 15;
        int token = b * SEQ + qb * 64 + row0 + r;
        float4 v = *(const float4*)(Q + (size_t)token * HIDDEN + h * HD + c4 * 4);
        uint4 u = { f2tf32(v.x), f2tf32(v.y), f2tf32(v.z), f2tf32(v.w) };
        *(uint4*)(Ss + (row0 + r) * FST + c4 * 4) = u;
    }
    __syncwarp();
    uint32_t qf[8][4];
    #pragma unroll
    for (int ks = 0; ks < 8; ks++) {
        const float* qp = Ss + (row0 + gid) * FST + ks * 8 + tid4;
        qf[ks][0] = __float_as_uint(qp[0]);
        qf[ks][1] = __float_as_uint(qp[8 * FST]);
        qf[ks][2] = __float_as_uint(qp[4]);
        qf[ks][3] = __float_as_uint(qp[8 * FST + 4]);
    }
    __syncwarp();

    float o[8][4];
    #pragma unroll
    for (int nt = 0; nt < 8; nt++)
        #pragma unroll
        for (int i = 0; i < 4; i++) o[nt][i] = 0.f;
    float m0 = -1e30f, m1 = -1e30f, l0 = 0.f, l1 = 0.f;

    for (int kt = 0; kt <= qb; kt++) {
        const int k0 = kt * 64;
        // Cooperative K/V tile load (tf32 at store).
        #pragma unroll
        for (int j = 0; j < 8; j++) {
            int idx = j * 128 + tid;
            int key = idx >> 4, c4 = idx & 15;
            size_t base = ((size_t)(b * SEQ + k0 + key) * NKV + hkv) * HD + c4 * 4;
            float4 kv = *(const float4*)(Kg + base);
            float4 vv = *(const float4*)(Vg + base);
            uint4 uk = { f2tf32(kv.x), f2tf32(kv.y), f2tf32(kv.z), f2tf32(kv.w) };
            uint4 uv = { f2tf32(vv.x), f2tf32(vv.y), f2tf32(vv.z), f2tf32(vv.w) };
            *(uint4*)(Ks + key * FST  + c4 * 4) = uk;
            *(uint4*)(Vs + key * FSTV + c4 * 4) = uv;
        }
        __syncthreads();

        // S = Q K^T  (this warp's 16x64 stripe)
        float c[8][4];
        #pragma unroll
        for (int nt = 0; nt < 8; nt++)
            #pragma unroll
            for (int i = 0; i < 4; i++) c[nt][i] = 0.f;
        #pragma unroll
        for (int ks = 0; ks < 8; ks++)
            #pragma unroll
            for (int nt = 0; nt < 8; nt++) {
                const float* bp = Ks + (nt * 8 + gid) * FST + ks * 8 + tid4;
                mma8(c[nt], qf[ks], __float_as_uint(bp[0]),
                     __float_as_uint(bp[4]));
            }

        // scale + causal mask (diagonal tile only)
        #pragma unroll
        for (int nt = 0; nt < 8; nt++)
            #pragma unroll
            for (int i = 0; i < 4; i++) c[nt][i] *= 0.125f;
        if (kt == qb) {
            const int r0l = row0 + gid, r1l = row0 + gid + 8;
            #pragma unroll
            for (int nt = 0; nt < 8; nt++) {
                int cb = nt * 8 + 2 * tid4;
                if (cb     > r0l) c[nt][0] = -1e30f;
                if (cb + 1 > r0l) c[nt][1] = -1e30f;
                if (cb     > r1l) c[nt][2] = -1e30f;
                if (cb + 1 > r1l) c[nt][3] = -1e30f;
            }
        }

        // online softmax (two rows per thread: gid and gid+8)
        float t0 = -1e30f, t1 = -1e30f;
        #pragma unroll
        for (int nt = 0; nt < 8; nt++) {
            t0 = fmaxf(t0, fmaxf(c[nt][0], c[nt][1]));
            t1 = fmaxf(t1, fmaxf(c[nt][2], c[nt][3]));
        }
        t0 = fmaxf(t0, __shfl_xor_sync(0xffffffffu, t0, 1));
        t0 = fmaxf(t0, __shfl_xor_sync(0xffffffffu, t0, 2));
        t1 = fmaxf(t1, __shfl_xor_sync(0xffffffffu, t1, 1));
        t1 = fmaxf(t1, __shfl_xor_sync(0xffffffffu, t1, 2));
        float m0n = fmaxf(m0, t0);
        float m1n = fmaxf(m1, t1);
        float cor0 = __expf(m0 - m0n);
        float cor1 = __expf(m1 - m1n);
        #pragma unroll
        for (int nt = 0; nt < 8; nt++) {
            o[nt][0] *= cor0; o[nt][1] *= cor0;
            o[nt][2] *= cor1; o[nt][3] *= cor1;
        }

        float s0 = 0.f, s1 = 0.f;
        #pragma unroll
        for (int nt = 0; nt < 8; nt++) {
            float p0 = __expf(c[nt][0] - m0n);
            float p1 = __expf(c[nt][1] - m0n);
            float p2 = __expf(c[nt][2] - m1n);
            float p3 = __expf(c[nt][3] - m1n);
            s0 += p0 + p1;
            s1 += p2 + p3;
            float2 w0 = { __uint_as_float(f2tf32(p0)), __uint_as_float(f2tf32(p1)) };
            float2 w1 = { __uint_as_float(f2tf32(p2)), __uint_as_float(f2tf32(p3)) };
            *(float2*)(Ss + (row0 + gid)     * FST + nt * 8 + 2 * tid4) = w0;
            *(float2*)(Ss + (row0 + gid + 8) * FST + nt * 8 + 2 * tid4) = w1;
        }
        s0 += __shfl_xor_sync(0xffffffffu, s0, 1);
        s0 += __shfl_xor_sync(0xffffffffu, s0, 2);
        s1 += __shfl_xor_sync(0xffffffffu, s1, 1);
        s1 += __shfl_xor_sync(0xffffffffu, s1, 2);
        l0 = l0 * cor0 + s0;
        l1 = l1 * cor1 + s1;
        m0 = m0n; m1 = m1n;
        __syncwarp();

        // O += P V
        #pragma unroll
        for (int ks = 0; ks < 8; ks++) {
            uint32_t a[4];
            const float* ap = Ss + (row0 + gid) * FST + ks * 8 + tid4;
            a[0] = __float_as_uint(ap[0]);
            a[1] = __float_as_uint(ap[8 * FST]);
            a[2] = __float_as_uint(ap[4]);
            a[3] = __float_as_uint(ap[8 * FST + 4]);
            #pragma unroll
            for (int nt = 0; nt < 8; nt++) {
                const float* vp = Vs + (ks * 8 + tid4) * FSTV + nt * 8 + gid;
                mma8(o[nt], a, __float_as_uint(vp[0]),
                     __float_as_uint(vp[4 * FSTV]));
            }
        }
        __syncthreads();
    }

    // normalize + store
    float inv0 = 1.f / l0, inv1 = 1.f / l1;
    int token0 = b * SEQ + qb * 64 + row0 + gid;
    float* op0 = O + (size_t)token0 * HIDDEN + h * HD;
    float* op1 = op0 + (size_t)8 * HIDDEN;
    #pragma unroll
    for (int nt = 0; nt < 8; nt++) {
        int col = nt * 8 + 2 * tid4;
        float2 v0 = { o[nt][0] * inv0, o[nt][1] * inv0 };
        float2 v1 = { o[nt][2] * inv1, o[nt][3] * inv1 };
        *(float2*)(op0 + col) = v0;
        *(float2*)(op1 + col) = v1;
    }
}

// ---------------------------------------------------------------------------
// Launch sequence
// ---------------------------------------------------------------------------
extern "C" void kernel_launch(void* const* d_in, const int* in_sizes, int n_in,
                              void* d_out, int out_size) {
    const float* x   = (const float*)d_in[0];
    const float* Wq  = (const float*)d_in[1];
    const float* Wk  = (const float*)d_in[2];
    const float* Wv  = (const float*)d_in[3];
    const float* Wo  = (const float*)d_in[4];
    const int*   pos = (const int*)d_in[5];
    float* out = (float*)d_out;

    float *Qp, *Kp, *Vp, *Op, *WtQ, *WtK, *WtV, *WtO;
    cudaGetSymbolAddress((void**)&Qp,  g_Q);
    cudaGetSymbolAddress((void**)&Kp,  g_K);
    cudaGetSymbolAddress((void**)&Vp,  g_V);
    cudaGetSymbolAddress((void**)&Op,  g_O);
    cudaGetSymbolAddress((void**)&WtQ, g_WtQ);
    cudaGetSymbolAddress((void**)&WtK, g_WtK);
    cudaGetSymbolAddress((void**)&WtV, g_WtV);
    cudaGetSymbolAddress((void**)&WtO, g_WtO);

    cudaFuncSetAttribute(gemm_mma, cudaFuncAttributeMaxDynamicSharedMemorySize,
                         GEMM_SMEM_BYTES);
    cudaFuncSetAttribute(flash_mma, cudaFuncAttributeMaxDynamicSharedMemorySize,
                         FLASH_SMEM);

    const int M = BSTOK;        // 4096
    dim3 tb(32, 8);

    transpose_k<<<dim3(HIDDEN / 32, HIDDEN / 32), tb>>>(Wq, WtQ, HIDDEN, HIDDEN);
    transpose_k<<<dim3((NKV * HD) / 32, HIDDEN / 32), tb>>>(Wk, WtK, HIDDEN, NKV * HD);
    transpose_k<<<dim3((NKV * HD) / 32, HIDDEN / 32), tb>>>(Wv, WtV, HIDDEN, NKV * HD);
    transpose_k<<<dim3(HIDDEN / 32, HIDDEN / 32), tb>>>(Wo, WtO, HIDDEN, HIDDEN);

    rope_table<<<(BSTOK * 32 + 255) / 256, 256>>>(pos);

    gemm_mma<<<dim3(HIDDEN / 128, M / 128), 256, GEMM_SMEM_BYTES>>>(
        x, WtQ, Qp, M, HIDDEN, HIDDEN);
    gemm_mma<<<dim3((NKV * HD) / 128, M / 128), 256, GEMM_SMEM_BYTES>>>(
        x, WtK, Kp, M, NKV * HD, HIDDEN);
    gemm_mma<<<dim3((NKV * HD) / 128, M / 128), 256, GEMM_SMEM_BYTES>>>(
        x, WtV, Vp, M, NKV * HD, HIDDEN);

    rope_apply<<<(BSTOK * NH * 32 + 255) / 256, 256>>>(Qp, NH);
    rope_apply<<<(BSTOK * NKV * 32 + 255) / 256, 256>>>(Kp, NKV);

    flash_mma<<<dim3(SEQ / 64, NH, BB), 128, FLASH_SMEM>>>(Qp, Kp, Vp, Op);

    gemm_mma<<<dim3(HIDDEN / 128, M / 128), 256, GEMM_SMEM_BYTES>>>(
        Op, WtO, out, M, HIDDEN, HIDDEN);
}

// round 6
// speedup vs baseline: 6.8360x; 1.7034x over previous
#include <cuda_runtime.h>
#include <cuda_fp16.h>
#include <math.h>
#include <stdint.h>

#define HIDDEN 2048
#define NH 32
#define NKV 8
#define HD 64
#define BB 2
#define SEQ 2048
#define BSTOK (BB*SEQ)

// ---------------------------------------------------------------------------
// Scratch (static device globals; no allocation allowed)
// ---------------------------------------------------------------------------
__device__ __half g_xh [(size_t)BSTOK * HIDDEN];
__device__ float  g_Q  [(size_t)BSTOK * HIDDEN];      // fp32 Q (pre-rope)
__device__ float  g_K  [(size_t)BSTOK * NKV * HD];    // fp32 K (pre-rope)
__device__ __half g_Qh [(size_t)BSTOK * HIDDEN];      // roped half
__device__ __half g_Kh [(size_t)BSTOK * NKV * HD];
__device__ __half g_Vh [(size_t)BSTOK * NKV * HD];
__device__ __half g_Oh [(size_t)BSTOK * HIDDEN];
__device__ __half g_WtQ[(size_t)HIDDEN * HIDDEN];     // W^T, half
__device__ __half g_WtK[(size_t)(NKV*HD) * HIDDEN];
__device__ __half g_WtV[(size_t)(NKV*HD) * HIDDEN];
__device__ __half g_WtO[(size_t)HIDDEN * HIDDEN];
__device__ float  g_cos[BSTOK * 32];
__device__ float  g_sin[BSTOK * 32];

// ---------------------------------------------------------------------------
// Helpers
// ---------------------------------------------------------------------------
__device__ __forceinline__ uint32_t smem_u32(const void* p) {
    uint32_t a;
    asm("{ .reg .u64 t; cvta.to.shared.u64 t, %1; cvt.u32.u64 %0, t; }"
        : "=r"(a) : "l"(p));
    return a;
}
__device__ __forceinline__ void ldsm4(uint32_t* r, uint32_t addr) {
    asm volatile("ldmatrix.sync.aligned.m8n8.x4.shared.b16 {%0,%1,%2,%3}, [%4];"
                 : "=r"(r[0]), "=r"(r[1]), "=r"(r[2]), "=r"(r[3]) : "r"(addr));
}
__device__ __forceinline__ void ldsm4t(uint32_t* r, uint32_t addr) {
    asm volatile("ldmatrix.sync.aligned.m8n8.x4.trans.shared.b16 {%0,%1,%2,%3}, [%4];"
                 : "=r"(r[0]), "=r"(r[1]), "=r"(r[2]), "=r"(r[3]) : "r"(addr));
}
__device__ __forceinline__ void mma16(float* c, const uint32_t* a,
                                      uint32_t b0, uint32_t b1) {
    asm volatile(
        "mma.sync.aligned.m16n8k16.row.col.f32.f16.f16.f32 "
        "{%0,%1,%2,%3}, {%4,%5,%6,%7}, {%8,%9}, {%0,%1,%2,%3};"
        : "+f"(c[0]), "+f"(c[1]), "+f"(c[2]), "+f"(c[3])
        : "r"(a[0]), "r"(a[1]), "r"(a[2]), "r"(a[3]), "r"(b0), "r"(b1));
}

// ---------------------------------------------------------------------------
// fp16 mma GEMM: C[M,N] = A[M,K] @ Bt[N,K]^T  (A, Bt half; C fp32 or half)
// CTA 128x128, 256 threads (8 warps, 2Mx4N), warp tile 64x32.
// K-chunk 32 (2 k16 steps), double-buffered smem, stride 40 halfs.
// ---------------------------------------------------------------------------
#define KST2 40
#define CHUNKH (128 * KST2)                 // halfs per tile-chunk
#define GEMM_SMEM_BYTES (4 * CHUNKH * 2)    // 40960 B

template<bool HOUT>
__global__ __launch_bounds__(256, 1) void gemm_h(
    const __half* __restrict__ A, const __half* __restrict__ Bt,
    void* __restrict__ Cv, int M, int N, int K) {
    extern __shared__ __half sh[];
    const uint32_t sbase = smem_u32(sh);
    const int tid  = threadIdx.x;
    const int wid  = tid >> 5;
    const int lane = tid & 31;
    const int gid  = lane >> 2;
    const int tid4 = lane & 3;
    const int wm   = wid & 1;
    const int wn   = wid >> 1;
    const int m0 = blockIdx.y * 128;
    const int n0 = blockIdx.x * 128;

    // ldmatrix lane addressing
    const int arow = (lane & 7) + ((lane >> 3) & 1) * 8;
    const int akof = (lane >> 4) * 8;
    const int brow = (lane & 7) + (lane >> 4) * 8;
    const int bkof = ((lane >> 3) & 1) * 8;

    // cooperative load: 2 uint4 per thread per tile per chunk
    int lrow[2], lv[2];
    #pragma unroll
    for (int i = 0; i < 2; i++) {
        int lin = i * 256 + tid;
        lrow[i] = lin >> 2;
        lv[i]   = lin & 3;
    }

    const __half* Ag = A  + (size_t)m0 * K;
    const __half* Bg = Bt + (size_t)n0 * K;

    float acc[4][4][4];
    #pragma unroll
    for (int mt = 0; mt < 4; mt++)
        #pragma unroll
        for (int nt = 0; nt < 4; nt++)
            #pragma unroll
            for (int c = 0; c < 4; c++) acc[mt][nt][c] = 0.f;

    // chunk 0
    #pragma unroll
    for (int i = 0; i < 2; i++) {
        *(uint4*)(sh + lrow[i] * KST2 + lv[i] * 8) =
            *(const uint4*)(Ag + (size_t)lrow[i] * K + lv[i] * 8);
        *(uint4*)(sh + CHUNKH + lrow[i] * KST2 + lv[i] * 8) =
            *(const uint4*)(Bg + (size_t)lrow[i] * K + lv[i] * 8);
    }
    __syncthreads();

    const int nch = K / 32;
    for (int ch = 0; ch < nch; ch++) {
        const int cur = ch & 1;
        const uint32_t As = sbase + cur * 2 * CHUNKH * 2;
        const uint32_t Bs = As + CHUNKH * 2;

        uint4 pa[2], pb[2];
        if (ch + 1 < nch) {
            const int kb = (ch + 1) * 32;
            #pragma unroll
            for (int i = 0; i < 2; i++) {
                pa[i] = *(const uint4*)(Ag + (size_t)lrow[i] * K + kb + lv[i] * 8);
                pb[i] = *(const uint4*)(Bg + (size_t)lrow[i] * K + kb + lv[i] * 8);
            }
        }

        #pragma unroll
        for (int ks = 0; ks < 2; ks++) {
            uint32_t af[4][4], bf[4][2];
            #pragma unroll
            for (int mt = 0; mt < 4; mt++)
                ldsm4(af[mt], As + ((wm * 64 + mt * 16 + arow) * KST2
                                    + ks * 16 + akof) * 2);
            #pragma unroll
            for (int p = 0; p < 2; p++) {
                uint32_t b4[4];
                ldsm4(b4, Bs + ((wn * 32 + p * 16 + brow) * KST2
                                + ks * 16 + bkof) * 2);
                bf[2 * p][0] = b4[0]; bf[2 * p][1] = b4[1];
                bf[2 * p + 1][0] = b4[2]; bf[2 * p + 1][1] = b4[3];
            }
            #pragma unroll
            for (int mt = 0; mt < 4; mt++)
                #pragma unroll
                for (int nt = 0; nt < 4; nt++)
                    mma16(acc[mt][nt], af[mt], bf[nt][0], bf[nt][1]);
        }

        if (ch + 1 < nch) {
            __half* An = sh + (1 - cur) * 2 * CHUNKH;
            __half* Bn = An + CHUNKH;
            #pragma unroll
            for (int i = 0; i < 2; i++) {
                *(uint4*)(An + lrow[i] * KST2 + lv[i] * 8) = pa[i];
                *(uint4*)(Bn + lrow[i] * KST2 + lv[i] * 8) = pb[i];
            }
        }
        __syncthreads();
    }

    // epilogue
    #pragma unroll
    for (int mt = 0; mt < 4; mt++) {
        const int r = m0 + wm * 64 + mt * 16 + gid;
        #pragma unroll
        for (int nt = 0; nt < 4; nt++) {
            const int col = n0 + wn * 32 + nt * 8 + tid4 * 2;
            if (HOUT) {
                __half* C = (__half*)Cv;
                *(__half2*)(C + (size_t)r * N + col) =
                    __floats2half2_rn(acc[mt][nt][0], acc[mt][nt][1]);
                *(__half2*)(C + (size_t)(r + 8) * N + col) =
                    __floats2half2_rn(acc[mt][nt][2], acc[mt][nt][3]);
            } else {
                float* C = (float*)Cv;
                float2 v0 = { acc[mt][nt][0], acc[mt][nt][1] };
                float2 v1 = { acc[mt][nt][2], acc[mt][nt][3] };
                *(float2*)(C + (size_t)r * N + col)       = v0;
                *(float2*)(C + (size_t)(r + 8) * N + col) = v1;
            }
        }
    }
}

// ---------------------------------------------------------------------------
// fp32 -> fp16 convert (x)
// ---------------------------------------------------------------------------
__global__ void convert_x(const float* __restrict__ X, __half* __restrict__ Xh,
                          int n4) {
    int idx = blockIdx.x * blockDim.x + threadIdx.x;
    if (idx >= n4) return;
    float4 v = ((const float4*)X)[idx];
    __half2 h0 = __floats2half2_rn(v.x, v.y);
    __half2 h1 = __floats2half2_rn(v.z, v.w);
    ((__half2*)Xh)[2 * idx]     = h0;
    ((__half2*)Xh)[2 * idx + 1] = h1;
}

// ---------------------------------------------------------------------------
// Weight transpose + convert: Wt[n][k] = (half)W[k][n]
// ---------------------------------------------------------------------------
__global__ void transpose_kh(const float* __restrict__ W, __half* __restrict__ Wt,
                             int R, int C) {
    __shared__ float tile[32][33];
    int c0 = blockIdx.x * 32, r0 = blockIdx.y * 32;
    int tx = threadIdx.x;
    for (int j = threadIdx.y; j < 32; j += 8)
        tile[j][tx] = W[(size_t)(r0 + j) * C + c0 + tx];
    __syncthreads();
    for (int j = threadIdx.y; j < 32; j += 8)
        Wt[(size_t)(c0 + j) * R + r0 + tx] = __float2half_rn(tile[tx][j]);
}

// ---------------------------------------------------------------------------
// RoPE table (fp64, tiny) + fp32->half roped apply
// ---------------------------------------------------------------------------
__global__ void rope_table(const int* __restrict__ pos) {
    int idx = blockIdx.x * blockDim.x + threadIdx.x;
    if (idx >= BSTOK * 32) return;
    int i = idx & 31, bs = idx >> 5;
    double inv_freq = exp(-(double)i * (9.210340371976184 / 32.0));
    double a = (double)pos[bs] * inv_freq;
    double s, c;
    sincos(a, &s, &c);
    g_cos[idx] = (float)c;
    g_sin[idx] = (float)s;
}

__global__ void rope_apply_h(const float* __restrict__ X,
                             __half* __restrict__ Xh, int nheads) {
    int idx = blockIdx.x * blockDim.x + threadIdx.x;
    int total = BSTOK * nheads * 32;
    if (idx >= total) return;
    int i  = idx & 31;
    int h  = (idx >> 5) % nheads;
    int bs = idx / (nheads * 32);
    float c  = g_cos[bs * 32 + i];
    float sn = g_sin[bs * 32 + i];
    const float* p = X + ((size_t)bs * nheads + h) * HD;
    __half* ph = Xh + ((size_t)bs * nheads + h) * HD;
    float x1 = p[i], x2 = p[i + 32];
    ph[i]      = __float2half_rn(x1 * c - x2 * sn);
    ph[i + 32] = __float2half_rn(x2 * c + x1 * sn);
}

// ---------------------------------------------------------------------------
// fp16 tensor-core causal flash attention.
// CTA: 64 queries (4 warps x 16 rows) x 64-key tiles, d=64, GQA 4:1.
// S = Q K^T and O += P V via mma.m16n8k16; ldmatrix fragments;
// V consumed via ldmatrix.trans (no transpose). Stride 72 halfs.
// ---------------------------------------------------------------------------
#define KSTH 72
#define FLASH_SMEM (3 * 64 * KSTH * 2)   // 27648 B

__global__ __launch_bounds__(128, 1) void flash_h(
    const __half* __restrict__ Qh, const __half* __restrict__ Kh,
    const __half* __restrict__ Vh, __half* __restrict__ Oh) {
    extern __shared__ __half fsh[];
    __half* Ks = fsh;                  // [64][72]
    __half* Vs = fsh + 64 * KSTH;      // [64][72]
    __half* Ss = Vs  + 64 * KSTH;      // [64][72] warp-private 16-row stripes
    const uint32_t ksb = smem_u32(Ks);
    const uint32_t vsb = smem_u32(Vs);
    const uint32_t ssb = smem_u32(Ss);

    const int tid  = threadIdx.x;
    const int warp = tid >> 5;
    const int lane = tid & 31;
    const int gid  = lane >> 2;
    const int tid4 = lane & 3;
    const int qb = blockIdx.x, h = blockIdx.y, b = blockIdx.z;
    const int hkv = h >> 2;
    const int row0 = warp * 16;

    // ldmatrix lane addressing
    const int arow = (lane & 7) + ((lane >> 3) & 1) * 8;   // A / P frags
    const int akof = (lane >> 4) * 8;
    const int brow = (lane & 7) + (lane >> 4) * 8;         // K (B, no trans)
    const int bkof = ((lane >> 3) & 1) * 8;
    const int vrow = (lane & 7) + ((lane >> 3) & 1) * 8;   // V (B, trans)
    const int vkof = (lane >> 4) * 8;

    // Stage Q stripe into this warp's Ss region, then cache fragments.
    #pragma unroll
    for (int j = 0; j < 4; j++) {
        int idx = j * 32 + lane;
        int r = idx >> 3, v = idx & 7;
        int token = b * SEQ + qb * 64 + row0 + r;
        *(uint4*)(Ss + (row0 + r) * KSTH + v * 8) =
            *(const uint4*)(Qh + (size_t)token * HIDDEN + h * HD + v * 8);
    }
    __syncwarp();
    uint32_t qf[4][4];
    #pragma unroll
    for (int ks = 0; ks < 4; ks++)
        ldsm4(qf[ks], ssb + ((row0 + arow) * KSTH + ks * 16 + akof) * 2);
    __syncwarp();

    float o[8][4];
    #pragma unroll
    for (int nt = 0; nt < 8; nt++)
        #pragma unroll
        for (int i = 0; i < 4; i++) o[nt][i] = 0.f;
    float m0 = -1e30f, m1 = -1e30f, l0 = 0.f, l1 = 0.f;

    for (int kt = 0; kt <= qb; kt++) {
        const int k0 = kt * 64;
        // Cooperative K/V tile load (half, vectorized)
        #pragma unroll
        for (int j = 0; j < 4; j++) {
            int idx = j * 128 + tid;
            int key = idx >> 3, v = idx & 7;
            size_t base = ((size_t)(b * SEQ + k0 + key) * NKV + hkv) * HD + v * 8;
            *(uint4*)(Ks + key * KSTH + v * 8) = *(const uint4*)(Kh + base);
            *(uint4*)(Vs + key * KSTH + v * 8) = *(const uint4*)(Vh + base);
        }
        __syncthreads();

        // S = Q K^T (16x64 stripe)
        float c[8][4];
        #pragma unroll
        for (int nt = 0; nt < 8; nt++)
            #pragma unroll
            for (int i = 0; i < 4; i++) c[nt][i] = 0.f;
        #pragma unroll
        for (int ks = 0; ks < 4; ks++)
            #pragma unroll
            for (int p = 0; p < 4; p++) {
                uint32_t b4[4];
                ldsm4(b4, ksb + ((p * 16 + brow) * KSTH + ks * 16 + bkof) * 2);
                mma16(c[2 * p],     qf[ks], b4[0], b4[1]);
                mma16(c[2 * p + 1], qf[ks], b4[2], b4[3]);
            }

        #pragma unroll
        for (int nt = 0; nt < 8; nt++)
            #pragma unroll
            for (int i = 0; i < 4; i++) c[nt][i] *= 0.125f;
        if (kt == qb) {
            const int r0l = row0 + gid, r1l = row0 + gid + 8;
            #pragma unroll
            for (int nt = 0; nt < 8; nt++) {
                int cb = nt * 8 + 2 * tid4;
                if (cb     > r0l) c[nt][0] = -1e30f;
                if (cb + 1 > r0l) c[nt][1] = -1e30f;
                if (cb     > r1l) c[nt][2] = -1e30f;
                if (cb + 1 > r1l) c[nt][3] = -1e30f;
            }
        }

        // online softmax (rows gid, gid+8)
        float t0 = -1e30f, t1 = -1e30f;
        #pragma unroll
        for (int nt = 0; nt < 8; nt++) {
            t0 = fmaxf(t0, fmaxf(c[nt][0], c[nt][1]));
            t1 = fmaxf(t1, fmaxf(c[nt][2], c[nt][3]));
        }
        t0 = fmaxf(t0, __shfl_xor_sync(0xffffffffu, t0, 1));
        t0 = fmaxf(t0, __shfl_xor_sync(0xffffffffu, t0, 2));
        t1 = fmaxf(t1, __shfl_xor_sync(0xffffffffu, t1, 1));
        t1 = fmaxf(t1, __shfl_xor_sync(0xffffffffu, t1, 2));
        float m0n = fmaxf(m0, t0);
        float m1n = fmaxf(m1, t1);
        float cor0 = __expf(m0 - m0n);
        float cor1 = __expf(m1 - m1n);
        #pragma unroll
        for (int nt = 0; nt < 8; nt++) {
            o[nt][0] *= cor0; o[nt][1] *= cor0;
            o[nt][2] *= cor1; o[nt][3] *= cor1;
        }

        float s0 = 0.f, s1 = 0.f;
        #pragma unroll
        for (int nt = 0; nt < 8; nt++) {
            float p0 = __expf(c[nt][0] - m0n);
            float p1 = __expf(c[nt][1] - m0n);
            float p2 = __expf(c[nt][2] - m1n);
            float p3 = __expf(c[nt][3] - m1n);
            s0 += p0 + p1;
            s1 += p2 + p3;
            *(__half2*)(Ss + (row0 + gid)     * KSTH + nt * 8 + 2 * tid4) =
                __floats2half2_rn(p0, p1);
            *(__half2*)(Ss + (row0 + gid + 8) * KSTH + nt * 8 + 2 * tid4) =
                __floats2half2_rn(p2, p3);
        }
        s0 += __shfl_xor_sync(0xffffffffu, s0, 1);
        s0 += __shfl_xor_sync(0xffffffffu, s0, 2);
        s1 += __shfl_xor_sync(0xffffffffu, s1, 1);
        s1 += __shfl_xor_sync(0xffffffffu, s1, 2);
        l0 = l0 * cor0 + s0;
        l1 = l1 * cor1 + s1;
        m0 = m0n; m1 = m1n;
        __syncwarp();

        // O += P V  (P from Ss, V via ldmatrix.trans)
        #pragma unroll
        for (int ks = 0; ks < 4; ks++) {
            uint32_t a4[4];
            ldsm4(a4, ssb + ((row0 + arow) * KSTH + ks * 16 + akof) * 2);
            #pragma unroll
            for (int p = 0; p < 4; p++) {
                uint32_t b4[4];
                ldsm4t(b4, vsb + ((ks * 16 + vrow) * KSTH + p * 16 + vkof) * 2);
                mma16(o[2 * p],     a4, b4[0], b4[1]);
                mma16(o[2 * p + 1], a4, b4[2], b4[3]);
            }
        }
        __syncthreads();
    }

    // normalize + store (half)
    float inv0 = 1.f / l0, inv1 = 1.f / l1;
    int token0 = b * SEQ + qb * 64 + row0 + gid;
    __half* op0 = Oh + (size_t)token0 * HIDDEN + h * HD;
    __half* op1 = op0 + (size_t)8 * HIDDEN;
    #pragma unroll
    for (int nt = 0; nt < 8; nt++) {
        int col = nt * 8 + 2 * tid4;
        *(__half2*)(op0 + col) = __floats2half2_rn(o[nt][0] * inv0, o[nt][1] * inv0);
        *(__half2*)(op1 + col) = __floats2half2_rn(o[nt][2] * inv1, o[nt][3] * inv1);
    }
}

// ---------------------------------------------------------------------------
// Launch sequence
// ---------------------------------------------------------------------------
extern "C" void kernel_launch(void* const* d_in, const int* in_sizes, int n_in,
                              void* d_out, int out_size) {
    const float* x   = (const float*)d_in[0];
    const float* Wq  = (const float*)d_in[1];
    const float* Wk  = (const float*)d_in[2];
    const float* Wv  = (const float*)d_in[3];
    const float* Wo  = (const float*)d_in[4];
    const int*   pos = (const int*)d_in[5];
    float* out = (float*)d_out;

    __half *xh, *Qh, *Kh, *Vh, *Oh, *WtQ, *WtK, *WtV, *WtO;
    float *Qp, *Kp;
    cudaGetSymbolAddress((void**)&xh,  g_xh);
    cudaGetSymbolAddress((void**)&Qp,  g_Q);
    cudaGetSymbolAddress((void**)&Kp,  g_K);
    cudaGetSymbolAddress((void**)&Qh,  g_Qh);
    cudaGetSymbolAddress((void**)&Kh,  g_Kh);
    cudaGetSymbolAddress((void**)&Vh,  g_Vh);
    cudaGetSymbolAddress((void**)&Oh,  g_Oh);
    cudaGetSymbolAddress((void**)&WtQ, g_WtQ);
    cudaGetSymbolAddress((void**)&WtK, g_WtK);
    cudaGetSymbolAddress((void**)&WtV, g_WtV);
    cudaGetSymbolAddress((void**)&WtO, g_WtO);

    const int M = BSTOK;        // 4096
    dim3 tb(32, 8);

    // Convert x, transpose+convert weights, RoPE table
    convert_x<<<(BSTOK * HIDDEN / 4 + 255) / 256, 256>>>(x, xh, BSTOK * HIDDEN / 4);
    transpose_kh<<<dim3(HIDDEN / 32, HIDDEN / 32), tb>>>(Wq, WtQ, HIDDEN, HIDDEN);
    transpose_kh<<<dim3((NKV * HD) / 32, HIDDEN / 32), tb>>>(Wk, WtK, HIDDEN, NKV * HD);
    transpose_kh<<<dim3((NKV * HD) / 32, HIDDEN / 32), tb>>>(Wv, WtV, HIDDEN, NKV * HD);
    transpose_kh<<<dim3(HIDDEN / 32, HIDDEN / 32), tb>>>(Wo, WtO, HIDDEN, HIDDEN);
    rope_table<<<(BSTOK * 32 + 255) / 256, 256>>>(pos);

    // QKV projections (fp16 mma)
    gemm_h<false><<<dim3(HIDDEN / 128, M / 128), 256, GEMM_SMEM_BYTES>>>(
        xh, WtQ, Qp, M, HIDDEN, HIDDEN);
    gemm_h<false><<<dim3((NKV * HD) / 128, M / 128), 256, GEMM_SMEM_BYTES>>>(
        xh, WtK, Kp, M, NKV * HD, HIDDEN);
    gemm_h<true><<<dim3((NKV * HD) / 128, M / 128), 256, GEMM_SMEM_BYTES>>>(
        xh, WtV, Vh, M, NKV * HD, HIDDEN);

    // RoPE apply (fp32 in, half out)
    rope_apply_h<<<(BSTOK * NH * 32 + 255) / 256, 256>>>(Qp, Qh, NH);
    rope_apply_h<<<(BSTOK * NKV * 32 + 255) / 256, 256>>>(Kp, Kh, NKV);

    // Causal flash attention (fp16 mma)
    flash_h<<<dim3(SEQ / 64, NH, BB), 128, FLASH_SMEM>>>(Qh, Kh, Vh, Oh);

    // Output projection (half in, fp32 out)
    gemm_h<false><<<dim3(HIDDEN / 128, M / 128), 256, GEMM_SMEM_BYTES>>>(
        Oh, WtO, out, M, HIDDEN, HIDDEN);
}